// round 13
// baseline (speedup 1.0000x reference)
#include <cuda_runtime.h>
#include <cuda_bf16.h>
#include <cstdint>

// SlidingWindowAttention B=4,S=4096,E=1024,W=256 fp32 — mma.sync bf16-split (HMMA)
// with cp.async double-buffered staging pipelines.
// conv: Q/K/V fp32 -> bf16 hi/lo scratch (DRAM-bound, at floor).
// KA:   S=Q@K^T (3-split), mask+exp2 (no max-shift; logits bounded), P hi/lo ->
//       scratch in A-fragment layout; row sums -> g_linv.
// KB:   O = P@V (3-split), 256-e output chunks (4x P re-read, not 8x),
//       V double-buffered at HALF-TILE (64-key) granularity, scaled by 1/l.

#define S_LEN 4096
#define B_DIM 4
#define E_CH  1024
#define WND   256
#define NTIL  5
#define LOG2E_F 1.4426950408889634f
#define NELEM (B_DIM*S_LEN*E_CH)

__device__ __nv_bfloat16 g_Qh[NELEM], g_Ql[NELEM];
__device__ __nv_bfloat16 g_Kh[NELEM], g_Kl[NELEM];
__device__ __nv_bfloat16 g_Vh[NELEM], g_Vl[NELEM];
__device__ uint32_t g_Ph[B_DIM*32*NTIL*8*8*32*4];   // [b][qb][tile][w][kb][lane][4]
__device__ uint32_t g_Pl[B_DIM*32*NTIL*8*8*32*4];
__device__ float    g_linv[B_DIM*S_LEN];

__device__ __forceinline__ uint32_t smem_u32(const void* p){
    uint32_t a; asm("{ .reg .u64 t; cvta.to.shared.u64 t, %1; cvt.u32.u64 %0, t; }":"=r"(a):"l"(p)); return a;
}
__device__ __forceinline__ void ldsm4(uint32_t addr, uint32_t r[4]){
    asm volatile("ldmatrix.sync.aligned.m8n8.x4.shared.b16 {%0,%1,%2,%3}, [%4];"
        : "=r"(r[0]),"=r"(r[1]),"=r"(r[2]),"=r"(r[3]) : "r"(addr));
}
__device__ __forceinline__ void ldsm4t(uint32_t addr, uint32_t r[4]){
    asm volatile("ldmatrix.sync.aligned.m8n8.x4.trans.shared.b16 {%0,%1,%2,%3}, [%4];"
        : "=r"(r[0]),"=r"(r[1]),"=r"(r[2]),"=r"(r[3]) : "r"(addr));
}
__device__ __forceinline__ void mma16816(float c[4], const uint32_t a[4], uint32_t b0, uint32_t b1){
    asm volatile("mma.sync.aligned.m16n8k16.row.col.f32.bf16.bf16.f32 "
        "{%0,%1,%2,%3}, {%4,%5,%6,%7}, {%8,%9}, {%0,%1,%2,%3};"
        : "+f"(c[0]),"+f"(c[1]),"+f"(c[2]),"+f"(c[3])
        : "r"(a[0]),"r"(a[1]),"r"(a[2]),"r"(a[3]), "r"(b0),"r"(b1));
}
__device__ __forceinline__ void cpa16(uint32_t dst, const void* src){
    asm volatile("cp.async.cg.shared.global [%0], [%1], 16;" :: "r"(dst), "l"(src) : "memory");
}
#define CP_COMMIT() asm volatile("cp.async.commit_group;" ::: "memory")
#define CP_WAIT(n)  asm volatile("cp.async.wait_group %0;" :: "n"(n) : "memory")

__device__ __forceinline__ void spl(float x, unsigned short& h, unsigned short& l){
    __nv_bfloat16 hb = __float2bfloat16(x);
    h = __bfloat16_as_ushort(hb);
    l = __bfloat16_as_ushort(__float2bfloat16(x - __bfloat162float(hb)));
}
__device__ __forceinline__ uint32_t pack2(float a, float b, uint32_t& lo){
    unsigned short ha, la, hb2, lb2; spl(a, ha, la); spl(b, hb2, lb2);
    lo = (uint32_t)la | ((uint32_t)lb2 << 16);
    return (uint32_t)ha | ((uint32_t)hb2 << 16);
}

// ================= conversion kernel =================
__global__ __launch_bounds__(256) void conv_split(const float* __restrict__ q,
                                                  const float* __restrict__ k,
                                                  const float* __restrict__ v)
{
    int i = (blockIdx.x * 256 + threadIdx.x) * 4;
    if (i >= NELEM) return;
    float4 a = *(const float4*)(q + i);
    float4 b = *(const float4*)(k + i);
    float4 c = *(const float4*)(v + i);
    ushort4 h, l;
    spl(a.x, h.x, l.x); spl(a.y, h.y, l.y); spl(a.z, h.z, l.z); spl(a.w, h.w, l.w);
    *(ushort4*)(g_Qh + i) = h; *(ushort4*)(g_Ql + i) = l;
    spl(b.x, h.x, l.x); spl(b.y, h.y, l.y); spl(b.z, h.z, l.z); spl(b.w, h.w, l.w);
    *(ushort4*)(g_Kh + i) = h; *(ushort4*)(g_Kl + i) = l;
    spl(c.x, h.x, l.x); spl(c.y, h.y, l.y); spl(c.z, h.z, l.z); spl(c.w, h.w, l.w);
    *(ushort4*)(g_Vh + i) = h; *(ushort4*)(g_Vl + i) = l;
}

// ================= kernel A: scores + softmax -> P =================
// per-buffer (bf16, 144B/row stride): Qh@0, Ql@18432, Kh@36864, Kl@55296 (73728B)
// two buffers + mask f32
#define KA_QH 0
#define KA_QL 18432
#define KA_KH 36864
#define KA_KL 55296
#define KA_BUF 73728
#define KA_MSK (2*KA_BUF)
#define KA_SMEM (2*KA_BUF + 512)

__device__ __forceinline__ void ka_prefetch(uint32_t smb, int buf, int ec,
                                            int b, int q0, int j0, int t)
{
    const uint32_t bb = smb + (uint32_t)buf * KA_BUF;
    #pragma unroll
    for (int i = 0; i < 4; i++) {
        int idx = t + i * 256;             // 0..1023
        int row = idx >> 3, seg = idx & 7;
        long qsrc = ((long)(b * S_LEN + q0 + row)) * E_CH + ec * 64 + seg * 8;
        int jj = j0 + row; jj = jj < 0 ? 0 : (jj >= S_LEN ? S_LEN - 1 : jj);
        long ksrc = ((long)(b * S_LEN + jj)) * E_CH + ec * 64 + seg * 8;
        uint32_t dst = (uint32_t)(row * 144 + seg * 16);
        cpa16(bb + KA_QH + dst, g_Qh + qsrc);
        cpa16(bb + KA_QL + dst, g_Ql + qsrc);
        cpa16(bb + KA_KH + dst, g_Kh + ksrc);
        cpa16(bb + KA_KL + dst, g_Kl + ksrc);
    }
}

__global__ __launch_bounds__(256, 1)
void swa_scores(const int* __restrict__ maskg)
{
    extern __shared__ char sm[];
    const uint32_t smb = smem_u32(sm);
    float* mskS = (float*)(sm + KA_MSK);

    const int t = threadIdx.x, w = t >> 5, lane = t & 31;
    const int qb = blockIdx.x, b = blockIdx.y;
    const int q0 = qb * 128;
    const float scale2 = (1.0f / 32.0f) * LOG2E_F;

    float sum_lo = 0.0f, sum_hi = 0.0f;
    const int q_lo = q0 + w * 16 + (lane >> 2);
    const int q_hi = q_lo + 8;

    for (int tile = 0; tile < NTIL; tile++) {
        const int j0 = q0 - WND + tile * 128;
        __syncthreads();                       // prior epilogue done with mskS; bufs idle
        if (t < 128) {
            int j = j0 + t;
            mskS[t] = (j >= 0 && j < S_LEN && maskg[(long)b * S_LEN + j] != 0) ? 1.0f : 0.0f;
        }

        float c[16][4];
        #pragma unroll
        for (int n = 0; n < 16; n++) { c[n][0]=0.f; c[n][1]=0.f; c[n][2]=0.f; c[n][3]=0.f; }

        ka_prefetch(smb, 0, 0, b, q0, j0, t); CP_COMMIT();

        for (int ec = 0; ec < 16; ec++) {      // 64-e chunks, double-buffered
            if (ec < 15) { ka_prefetch(smb, (ec + 1) & 1, ec + 1, b, q0, j0, t); CP_COMMIT(); }
            if (ec < 15) CP_WAIT(1); else CP_WAIT(0);
            __syncthreads();

            const uint32_t bb = smb + (uint32_t)(ec & 1) * KA_BUF;
            const uint32_t arow = (uint32_t)(w * 16 + (lane & 15));
            for (int kb = 0; kb < 4; kb++) {
                uint32_t aoff = arow * 144 + kb * 32 + (lane >> 4) * 16;
                uint32_t ah[4], al[4];
                ldsm4(bb + KA_QH + aoff, ah);
                ldsm4(bb + KA_QL + aoff, al);
                #pragma unroll
                for (int nbp = 0; nbp < 8; nbp++) {
                    uint32_t brow = (uint32_t)(nbp * 16 + (lane & 7) + ((lane & 16) >> 1));
                    uint32_t boff = brow * 144 + kb * 32 + ((lane >> 3) & 1) * 16;
                    uint32_t bh[4], bl[4];
                    ldsm4(bb + KA_KH + boff, bh);
                    ldsm4(bb + KA_KL + boff, bl);
                    mma16816(c[2*nbp  ], ah, bh[0], bh[1]);
                    mma16816(c[2*nbp+1], ah, bh[2], bh[3]);
                    mma16816(c[2*nbp  ], ah, bl[0], bl[1]);
                    mma16816(c[2*nbp+1], ah, bl[2], bl[3]);
                    mma16816(c[2*nbp  ], al, bh[0], bh[1]);
                    mma16816(c[2*nbp+1], al, bh[2], bh[3]);
                }
            }
            __syncthreads();                   // buf free for the prefetch of ec+2
        }

        // ---- epilogue: mask + exp2, pack P A-frags, store ----
        #pragma unroll
        for (int kb = 0; kb < 8; kb++) {
            float p[8];
            #pragma unroll
            for (int half = 0; half < 2; half++) {
                int nb = 2 * kb + half;
                int col0 = j0 + nb * 8 + 2 * (lane & 3);
                float mk0 = mskS[nb * 8 + 2 * (lane & 3)];
                float mk1 = mskS[nb * 8 + 2 * (lane & 3) + 1];
                bool ok00 = (mk0 > 0.5f) && (abs(q_lo - col0)     <= WND);
                bool ok01 = (mk1 > 0.5f) && (abs(q_lo - col0 - 1) <= WND);
                bool ok10 = (mk0 > 0.5f) && (abs(q_hi - col0)     <= WND);
                bool ok11 = (mk1 > 0.5f) && (abs(q_hi - col0 - 1) <= WND);
                p[half*4+0] = ok00 ? exp2f(c[nb][0] * scale2) : 0.0f;
                p[half*4+1] = ok01 ? exp2f(c[nb][1] * scale2) : 0.0f;
                p[half*4+2] = ok10 ? exp2f(c[nb][2] * scale2) : 0.0f;
                p[half*4+3] = ok11 ? exp2f(c[nb][3] * scale2) : 0.0f;
            }
            sum_lo += p[0] + p[1] + p[4] + p[5];
            sum_hi += p[2] + p[3] + p[6] + p[7];
            uint32_t hr[4], lr[4];
            hr[0] = pack2(p[0], p[1], lr[0]);
            hr[1] = pack2(p[2], p[3], lr[1]);
            hr[2] = pack2(p[4], p[5], lr[2]);
            hr[3] = pack2(p[6], p[7], lr[3]);
            uint32_t idx4 = ((uint32_t)((((b * 32 + qb) * NTIL + tile) * 8 + w) * 8 + kb) * 32 + lane) * 4;
            *(uint4*)(g_Ph + idx4) = make_uint4(hr[0], hr[1], hr[2], hr[3]);
            *(uint4*)(g_Pl + idx4) = make_uint4(lr[0], lr[1], lr[2], lr[3]);
        }
    }
    sum_lo += __shfl_xor_sync(0xffffffffu, sum_lo, 1);
    sum_lo += __shfl_xor_sync(0xffffffffu, sum_lo, 2);
    sum_hi += __shfl_xor_sync(0xffffffffu, sum_hi, 1);
    sum_hi += __shfl_xor_sync(0xffffffffu, sum_hi, 2);
    if ((lane & 3) == 0) {
        g_linv[(long)b * S_LEN + q_lo] = (sum_lo > 0.0f) ? (1.0f / sum_lo) : 0.0f;
        g_linv[(long)b * S_LEN + q_hi] = (sum_hi > 0.0f) ? (1.0f / sum_hi) : 0.0f;
    }
}

// ================= kernel B: O = P @ V =================
// 256-e output chunks; V staged per HALF-TILE (64 keys x 256 e), double-buffered.
// per-buffer: Vh@0, Vl@33792 (64 rows x 264 bf16 = 528B/row); two buffers = 132KB
#define KB_VH 0
#define KB_VL 33792
#define KB_BUF 67584
#define KB_SMEM (2*KB_BUF)

// half-index h in [0,10): tile = h>>1, sub-half = h&1 (keys j0+sub*64 .. +63)
__device__ __forceinline__ void kb_prefetch(uint32_t smb, int buf, int h, int e0,
                                            int b, int q0, int t)
{
    const int j0 = q0 - WND + (h >> 1) * 128 + (h & 1) * 64;
    const uint32_t bb = smb + (uint32_t)buf * KB_BUF;
    #pragma unroll
    for (int i = 0; i < 8; i++) {
        int idx = t + i * 256;              // 0..2047
        int k = idx >> 5, seg = idx & 31;   // 64 keys x 32 segs(16B) = 2048
        int jj = j0 + k; jj = jj < 0 ? 0 : (jj >= S_LEN ? S_LEN - 1 : jj);
        long src = ((long)(b * S_LEN + jj)) * E_CH + e0 + seg * 8;
        uint32_t dst = (uint32_t)(k * 528 + seg * 16);
        cpa16(bb + KB_VH + dst, g_Vh + src);
        cpa16(bb + KB_VL + dst, g_Vl + src);
    }
}

__global__ __launch_bounds__(256, 1)
void swa_pv(float* __restrict__ Og)
{
    extern __shared__ char sm[];
    const uint32_t smb = smem_u32(sm);

    const int t = threadIdx.x, w = t >> 5, lane = t & 31;
    const int qb = blockIdx.x, b = blockIdx.y;
    const int q0 = qb * 128;

    const int q_lo = q0 + w * 16 + (lane >> 2);
    const float linv_lo = g_linv[(long)b * S_LEN + q_lo];
    const float linv_hi = g_linv[(long)b * S_LEN + q_lo + 8];

    for (int ec4 = 0; ec4 < 4; ec4++) {        // 256-e output chunks
        const int e0 = ec4 * 256;
        float c[32][4];
        #pragma unroll
        for (int n = 0; n < 32; n++) { c[n][0]=0.f; c[n][1]=0.f; c[n][2]=0.f; c[n][3]=0.f; }

        kb_prefetch(smb, 0, 0, e0, b, q0, t); CP_COMMIT();

        for (int h = 0; h < 2 * NTIL; h++) {   // 10 half-tiles, double-buffered
            if (h < 2 * NTIL - 1) { kb_prefetch(smb, (h + 1) & 1, h + 1, e0, b, q0, t); CP_COMMIT(); }
            if (h < 2 * NTIL - 1) CP_WAIT(1); else CP_WAIT(0);
            __syncthreads();

            const uint32_t bb = smb + (uint32_t)(h & 1) * KB_BUF;
            const int tile = h >> 1, hs = h & 1;
            for (int kbl = 0; kbl < 4; kbl++) {
                const int kb = hs * 4 + kbl;
                uint32_t idx4 = ((uint32_t)((((b * 32 + qb) * NTIL + tile) * 8 + w) * 8 + kb) * 32 + lane) * 4;
                uint4 h4 = *(const uint4*)(g_Ph + idx4);
                uint4 l4 = *(const uint4*)(g_Pl + idx4);
                uint32_t ph[4] = {h4.x, h4.y, h4.z, h4.w};
                uint32_t pl[4] = {l4.x, l4.y, l4.z, l4.w};
                uint32_t vrow = (uint32_t)(kbl * 16 + (lane & 7) + ((lane >> 3) & 1) * 8);
                #pragma unroll
                for (int nbp = 0; nbp < 16; nbp++) {
                    uint32_t voff = vrow * 528 + (nbp * 16 + (lane >> 4) * 8) * 2;
                    uint32_t bh[4], bl[4];
                    ldsm4t(bb + KB_VH + voff, bh);
                    ldsm4t(bb + KB_VL + voff, bl);
                    mma16816(c[2*nbp  ], ph, bh[0], bh[1]);
                    mma16816(c[2*nbp+1], ph, bh[2], bh[3]);
                    mma16816(c[2*nbp  ], ph, bl[0], bl[1]);
                    mma16816(c[2*nbp+1], ph, bl[2], bl[3]);
                    mma16816(c[2*nbp  ], pl, bh[0], bh[1]);
                    mma16816(c[2*nbp+1], pl, bh[2], bh[3]);
                }
            }
            __syncthreads();                   // buf free for next prefetch
        }

        // ---- epilogue: scale rows by 1/l, store this 256-e chunk ----
        float* out_lo = Og + ((long)(b * S_LEN + q_lo)) * E_CH;
        float* out_hi = out_lo + 8L * E_CH;
        #pragma unroll
        for (int nb = 0; nb < 32; nb++) {
            int col = e0 + nb * 8 + 2 * (lane & 3);
            *(float2*)(out_lo + col) = make_float2(c[nb][0] * linv_lo, c[nb][1] * linv_lo);
            *(float2*)(out_hi + col) = make_float2(c[nb][2] * linv_hi, c[nb][3] * linv_hi);
        }
    }
}

// ================= launch =================
extern "C" void kernel_launch(void* const* d_in, const int* in_sizes, int n_in,
                              void* d_out, int out_size)
{
    const float* Q = (const float*)d_in[0];
    const float* K = (const float*)d_in[1];
    const float* V = (const float*)d_in[2];
    const int*   M = (const int*)d_in[3];
    float* Out = (float*)d_out;

    cudaFuncSetAttribute(swa_scores, cudaFuncAttributeMaxDynamicSharedMemorySize, KA_SMEM);
    cudaFuncSetAttribute(swa_pv,     cudaFuncAttributeMaxDynamicSharedMemorySize, KB_SMEM);

    conv_split<<<NELEM / (256 * 4), 256>>>(Q, K, V);
    dim3 grid(32, B_DIM);
    swa_scores<<<grid, 256, KA_SMEM>>>(M);
    swa_pv<<<grid, 256, KB_SMEM>>>(Out);
}

// round 15
// speedup vs baseline: 1.1159x; 1.1159x over previous
#include <cuda_runtime.h>
#include <cuda_bf16.h>
#include <cstdint>

// SlidingWindowAttention B=4,S=4096,E=1024,W=256 fp32 — mma.sync bf16-split (HMMA).
// conv: Q/K/V fp32 -> bf16 hi/lo scratch (DRAM-bound, at floor).
// KA:   grid (32 qb, 5 tile, 4 b). One CTA = one 128x128 S tile over 16 e-chunks.
//       3-split HMMA, band-skip of fully-masked 16x16 blocks (tiles 0/4),
//       mask+exp2 (no max-shift; logits bounded), P hi/lo -> scratch in
//       A-fragment layout; per-tile l partials -> g_lpart (deterministic).
// KB:   grid (32 qb, 8 e-chunk, 4 b). One CTA = 128q x 128e output chunk over
//       5 key tiles; V via ldmatrix.trans; band-skip; scaled by 1/sum(lpart).
// Both GEMM kernels: single-buffer staging + __launch_bounds__(256,2) so two
// CTAs per SM overlap staging with the other CTA's MMAs.

#define S_LEN 4096
#define B_DIM 4
#define E_CH  1024
#define WND   256
#define NTIL  5
#define LOG2E_F 1.4426950408889634f
#define NELEM (B_DIM*S_LEN*E_CH)

__device__ __nv_bfloat16 g_Qh[NELEM], g_Ql[NELEM];
__device__ __nv_bfloat16 g_Kh[NELEM], g_Kl[NELEM];
__device__ __nv_bfloat16 g_Vh[NELEM], g_Vl[NELEM];
__device__ uint32_t g_Ph[B_DIM*32*NTIL*8*8*32*4];   // [b][qb][tile][w][kb][lane][4]
__device__ uint32_t g_Pl[B_DIM*32*NTIL*8*8*32*4];
__device__ float    g_lpart[B_DIM*32*NTIL*128];     // per-tile row sums

__device__ __forceinline__ uint32_t smem_u32(const void* p){
    uint32_t a; asm("{ .reg .u64 t; cvta.to.shared.u64 t, %1; cvt.u32.u64 %0, t; }":"=r"(a):"l"(p)); return a;
}
__device__ __forceinline__ void ldsm4(uint32_t addr, uint32_t r[4]){
    asm volatile("ldmatrix.sync.aligned.m8n8.x4.shared.b16 {%0,%1,%2,%3}, [%4];"
        : "=r"(r[0]),"=r"(r[1]),"=r"(r[2]),"=r"(r[3]) : "r"(addr));
}
__device__ __forceinline__ void ldsm4t(uint32_t addr, uint32_t r[4]){
    asm volatile("ldmatrix.sync.aligned.m8n8.x4.trans.shared.b16 {%0,%1,%2,%3}, [%4];"
        : "=r"(r[0]),"=r"(r[1]),"=r"(r[2]),"=r"(r[3]) : "r"(addr));
}
__device__ __forceinline__ void mma16816(float c[4], const uint32_t a[4], uint32_t b0, uint32_t b1){
    asm volatile("mma.sync.aligned.m16n8k16.row.col.f32.bf16.bf16.f32 "
        "{%0,%1,%2,%3}, {%4,%5,%6,%7}, {%8,%9}, {%0,%1,%2,%3};"
        : "+f"(c[0]),"+f"(c[1]),"+f"(c[2]),"+f"(c[3])
        : "r"(a[0]),"r"(a[1]),"r"(a[2]),"r"(a[3]), "r"(b0),"r"(b1));
}
__device__ __forceinline__ void cpa16(uint32_t dst, const void* src){
    asm volatile("cp.async.cg.shared.global [%0], [%1], 16;" :: "r"(dst), "l"(src) : "memory");
}
#define CP_COMMIT() asm volatile("cp.async.commit_group;" ::: "memory")
#define CP_WAIT(n)  asm volatile("cp.async.wait_group %0;" :: "n"(n) : "memory")

__device__ __forceinline__ void spl(float x, unsigned short& h, unsigned short& l){
    __nv_bfloat16 hb = __float2bfloat16(x);
    h = __bfloat16_as_ushort(hb);
    l = __bfloat16_as_ushort(__float2bfloat16(x - __bfloat162float(hb)));
}
__device__ __forceinline__ uint32_t pack2(float a, float b, uint32_t& lo){
    unsigned short ha, la, hb2, lb2; spl(a, ha, la); spl(b, hb2, lb2);
    lo = (uint32_t)la | ((uint32_t)lb2 << 16);
    return (uint32_t)ha | ((uint32_t)hb2 << 16);
}

// ================= conversion kernel =================
__global__ __launch_bounds__(256) void conv_split(const float* __restrict__ q,
                                                  const float* __restrict__ k,
                                                  const float* __restrict__ v)
{
    int i = (blockIdx.x * 256 + threadIdx.x) * 4;
    if (i >= NELEM) return;
    float4 a = *(const float4*)(q + i);
    float4 b = *(const float4*)(k + i);
    float4 c = *(const float4*)(v + i);
    ushort4 h, l;
    spl(a.x, h.x, l.x); spl(a.y, h.y, l.y); spl(a.z, h.z, l.z); spl(a.w, h.w, l.w);
    *(ushort4*)(g_Qh + i) = h; *(ushort4*)(g_Ql + i) = l;
    spl(b.x, h.x, l.x); spl(b.y, h.y, l.y); spl(b.z, h.z, l.z); spl(b.w, h.w, l.w);
    *(ushort4*)(g_Kh + i) = h; *(ushort4*)(g_Kl + i) = l;
    spl(c.x, h.x, l.x); spl(c.y, h.y, l.y); spl(c.z, h.z, l.z); spl(c.w, h.w, l.w);
    *(ushort4*)(g_Vh + i) = h; *(ushort4*)(g_Vl + i) = l;
}

// ================= kernel A: one S tile + softmax -> P =================
// smem (bf16, 144B/row stride): Qh@0, Ql@18432, Kh@36864, Kl@55296; mask f32 @73728
#define KA_QH 0
#define KA_QL 18432
#define KA_KH 36864
#define KA_KL 55296
#define KA_SMEM (73728 + 512)

__global__ __launch_bounds__(256, 2)
void swa_scores(const int* __restrict__ maskg)
{
    extern __shared__ char sm[];
    const uint32_t smb = smem_u32(sm);
    float* mskS = (float*)(sm + 73728);

    const int t = threadIdx.x, w = t >> 5, lane = t & 31;
    const int qb = blockIdx.x, tile = blockIdx.y, b = blockIdx.z;
    const int q0 = qb * 128;
    const int j0 = q0 - WND + tile * 128;
    const float scale2 = (1.0f / 32.0f) * LOG2E_F;

    const int q_lo = q0 + w * 16 + (lane >> 2);
    const int q_hi = q_lo + 8;
    // band-skip rule for 16-key blocks (kb==nbp indexing):
    // tile 0: block all-masked iff kb < w ; tile NTIL-1: iff kb > w
    const int kb_lo = (tile == 0)        ? w : 0;
    const int kb_hi = (tile == NTIL - 1) ? w : 7;

    if (t < 128) {
        int j = j0 + t;
        mskS[t] = (j >= 0 && j < S_LEN && maskg[(long)b * S_LEN + j] != 0) ? 1.0f : 0.0f;
    }

    float c[16][4];
    #pragma unroll
    for (int n = 0; n < 16; n++) { c[n][0]=0.f; c[n][1]=0.f; c[n][2]=0.f; c[n][3]=0.f; }

    for (int ec = 0; ec < 16; ec++) {          // 64-e chunks, single buffer
        // stage Q and K chunks (bf16 hi/lo)
        #pragma unroll
        for (int i = 0; i < 4; i++) {
            int idx = t + i * 256;             // 0..1023
            int row = idx >> 3, seg = idx & 7;
            long qsrc = ((long)(b * S_LEN + q0 + row)) * E_CH + ec * 64 + seg * 8;
            int jj = j0 + row; jj = jj < 0 ? 0 : (jj >= S_LEN ? S_LEN - 1 : jj);
            long ksrc = ((long)(b * S_LEN + jj)) * E_CH + ec * 64 + seg * 8;
            uint32_t dst = (uint32_t)(row * 144 + seg * 16);
            cpa16(smb + KA_QH + dst, g_Qh + qsrc);
            cpa16(smb + KA_QL + dst, g_Ql + qsrc);
            cpa16(smb + KA_KH + dst, g_Kh + ksrc);
            cpa16(smb + KA_KL + dst, g_Kl + ksrc);
        }
        CP_COMMIT(); CP_WAIT(0);
        __syncthreads();

        const uint32_t arow = (uint32_t)(w * 16 + (lane & 15));
        for (int kbE = 0; kbE < 4; kbE++) {    // e sub-chunks of 16
            uint32_t aoff = arow * 144 + kbE * 32 + (lane >> 4) * 16;
            uint32_t ah[4], al[4];
            ldsm4(smb + KA_QH + aoff, ah);
            ldsm4(smb + KA_QL + aoff, al);
            #pragma unroll
            for (int nbp = 0; nbp < 8; nbp++) {
                if (nbp < kb_lo || nbp > kb_hi) continue;   // band-skip (warp-uniform)
                uint32_t brow = (uint32_t)(nbp * 16 + (lane & 7) + ((lane & 16) >> 1));
                uint32_t boff = brow * 144 + kbE * 32 + ((lane >> 3) & 1) * 16;
                uint32_t bh[4], bl[4];
                ldsm4(smb + KA_KH + boff, bh);
                ldsm4(smb + KA_KL + boff, bl);
                mma16816(c[2*nbp  ], ah, bh[0], bh[1]);
                mma16816(c[2*nbp+1], ah, bh[2], bh[3]);
                mma16816(c[2*nbp  ], ah, bl[0], bl[1]);
                mma16816(c[2*nbp+1], ah, bl[2], bl[3]);
                mma16816(c[2*nbp  ], al, bh[0], bh[1]);
                mma16816(c[2*nbp+1], al, bh[2], bh[3]);
            }
        }
        __syncthreads();                       // buffer free for next chunk's stores
    }

    // ---- epilogue: mask + exp2, pack P A-frags, store; l partials ----
    float sum_lo = 0.0f, sum_hi = 0.0f;
    #pragma unroll
    for (int kb = 0; kb < 8; kb++) {
        if (kb < kb_lo || kb > kb_hi) continue;            // skipped blocks: no store
        float p[8];
        #pragma unroll
        for (int half = 0; half < 2; half++) {
            int nb = 2 * kb + half;
            int col0 = j0 + nb * 8 + 2 * (lane & 3);
            float mk0 = mskS[nb * 8 + 2 * (lane & 3)];
            float mk1 = mskS[nb * 8 + 2 * (lane & 3) + 1];
            bool ok00 = (mk0 > 0.5f) && (abs(q_lo - col0)     <= WND);
            bool ok01 = (mk1 > 0.5f) && (abs(q_lo - col0 - 1) <= WND);
            bool ok10 = (mk0 > 0.5f) && (abs(q_hi - col0)     <= WND);
            bool ok11 = (mk1 > 0.5f) && (abs(q_hi - col0 - 1) <= WND);
            p[half*4+0] = ok00 ? exp2f(c[nb][0] * scale2) : 0.0f;
            p[half*4+1] = ok01 ? exp2f(c[nb][1] * scale2) : 0.0f;
            p[half*4+2] = ok10 ? exp2f(c[nb][2] * scale2) : 0.0f;
            p[half*4+3] = ok11 ? exp2f(c[nb][3] * scale2) : 0.0f;
        }
        sum_lo += p[0] + p[1] + p[4] + p[5];
        sum_hi += p[2] + p[3] + p[6] + p[7];
        uint32_t hr[4], lr[4];
        hr[0] = pack2(p[0], p[1], lr[0]);
        hr[1] = pack2(p[2], p[3], lr[1]);
        hr[2] = pack2(p[4], p[5], lr[2]);
        hr[3] = pack2(p[6], p[7], lr[3]);
        uint32_t idx4 = ((uint32_t)((((b * 32 + qb) * NTIL + tile) * 8 + w) * 8 + kb) * 32 + lane) * 4;
        *(uint4*)(g_Ph + idx4) = make_uint4(hr[0], hr[1], hr[2], hr[3]);
        *(uint4*)(g_Pl + idx4) = make_uint4(lr[0], lr[1], lr[2], lr[3]);
    }
    sum_lo += __shfl_xor_sync(0xffffffffu, sum_lo, 1);
    sum_lo += __shfl_xor_sync(0xffffffffu, sum_lo, 2);
    sum_hi += __shfl_xor_sync(0xffffffffu, sum_hi, 1);
    sum_hi += __shfl_xor_sync(0xffffffffu, sum_hi, 2);
    if ((lane & 3) == 0) {
        int base = ((b * 32 + qb) * NTIL + tile) * 128;
        g_lpart[base + w * 16 + (lane >> 2)]     = sum_lo;
        g_lpart[base + w * 16 + (lane >> 2) + 8] = sum_hi;
    }
}

// ================= kernel B: O chunk = P @ V =================
// smem single buffer: Vh@0, Vl@34816 (128 rows x 136 bf16 = 272B/row)
#define KB_VH 0
#define KB_VL 34816
#define KB_SMEM 69632

__global__ __launch_bounds__(256, 2)
void swa_pv(float* __restrict__ Og)
{
    extern __shared__ char sm[];
    const uint32_t smb = smem_u32(sm);

    const int t = threadIdx.x, w = t >> 5, lane = t & 31;
    const int qb = blockIdx.x, ec2 = blockIdx.y, b = blockIdx.z;
    const int q0 = qb * 128;
    const int e0 = ec2 * 128;

    const int row_lo = w * 16 + (lane >> 2);
    const int q_lo = q0 + row_lo;

    // l = sum of per-tile partials (deterministic, tile order)
    float l_lo = 0.0f, l_hi = 0.0f;
    #pragma unroll
    for (int tl = 0; tl < NTIL; tl++) {
        int base = ((b * 32 + qb) * NTIL + tl) * 128;
        l_lo += g_lpart[base + row_lo];
        l_hi += g_lpart[base + row_lo + 8];
    }
    const float linv_lo = (l_lo > 0.0f) ? (1.0f / l_lo) : 0.0f;
    const float linv_hi = (l_hi > 0.0f) ? (1.0f / l_hi) : 0.0f;

    float c[16][4];
    #pragma unroll
    for (int n = 0; n < 16; n++) { c[n][0]=0.f; c[n][1]=0.f; c[n][2]=0.f; c[n][3]=0.f; }

    for (int tile = 0; tile < NTIL; tile++) {
        const int j0 = q0 - WND + tile * 128;
        const int kb_lo = (tile == 0)        ? w : 0;
        const int kb_hi = (tile == NTIL - 1) ? w : 7;

        // stage V chunk hi/lo (single buffer)
        #pragma unroll
        for (int i = 0; i < 8; i++) {
            int idx = t + i * 256;              // 0..2047
            int k = idx >> 4, seg = idx & 15;   // 128 keys x 16 segs(16B)
            int jj = j0 + k; jj = jj < 0 ? 0 : (jj >= S_LEN ? S_LEN - 1 : jj);
            long src = ((long)(b * S_LEN + jj)) * E_CH + e0 + seg * 8;
            uint32_t dst = (uint32_t)(k * 272 + seg * 16);
            cpa16(smb + KB_VH + dst, g_Vh + src);
            cpa16(smb + KB_VL + dst, g_Vl + src);
        }
        CP_COMMIT(); CP_WAIT(0);
        __syncthreads();

        for (int kb = 0; kb < 8; kb++) {
            if (kb < kb_lo || kb > kb_hi) continue;        // band-skip (matches KA)
            uint32_t idx4 = ((uint32_t)((((b * 32 + qb) * NTIL + tile) * 8 + w) * 8 + kb) * 32 + lane) * 4;
            uint4 h4 = *(const uint4*)(g_Ph + idx4);
            uint4 l4 = *(const uint4*)(g_Pl + idx4);
            uint32_t ph[4] = {h4.x, h4.y, h4.z, h4.w};
            uint32_t pl[4] = {l4.x, l4.y, l4.z, l4.w};
            uint32_t vrow = (uint32_t)(kb * 16 + (lane & 7) + ((lane >> 3) & 1) * 8);
            #pragma unroll
            for (int nbp = 0; nbp < 8; nbp++) {
                uint32_t voff = vrow * 272 + (nbp * 16 + (lane >> 4) * 8) * 2;
                uint32_t bh[4], bl[4];
                ldsm4t(smb + KB_VH + voff, bh);
                ldsm4t(smb + KB_VL + voff, bl);
                mma16816(c[2*nbp  ], ph, bh[0], bh[1]);
                mma16816(c[2*nbp+1], ph, bh[2], bh[3]);
                mma16816(c[2*nbp  ], ph, bl[0], bl[1]);
                mma16816(c[2*nbp+1], ph, bl[2], bl[3]);
                mma16816(c[2*nbp  ], pl, bh[0], bh[1]);
                mma16816(c[2*nbp+1], pl, bh[2], bh[3]);
            }
        }
        __syncthreads();                       // buffer free for next tile's stores
    }

    // ---- epilogue: scale rows by 1/l, store this 128-e chunk ----
    float* out_lo = Og + ((long)(b * S_LEN + q_lo)) * E_CH;
    float* out_hi = out_lo + 8L * E_CH;
    #pragma unroll
    for (int nb = 0; nb < 16; nb++) {
        int col = e0 + nb * 8 + 2 * (lane & 3);
        *(float2*)(out_lo + col) = make_float2(c[nb][0] * linv_lo, c[nb][1] * linv_lo);
        *(float2*)(out_hi + col) = make_float2(c[nb][2] * linv_hi, c[nb][3] * linv_hi);
    }
}

// ================= launch =================
extern "C" void kernel_launch(void* const* d_in, const int* in_sizes, int n_in,
                              void* d_out, int out_size)
{
    const float* Q = (const float*)d_in[0];
    const float* K = (const float*)d_in[1];
    const float* V = (const float*)d_in[2];
    const int*   M = (const int*)d_in[3];
    float* Out = (float*)d_out;

    cudaFuncSetAttribute(swa_scores, cudaFuncAttributeMaxDynamicSharedMemorySize, KA_SMEM);
    cudaFuncSetAttribute(swa_pv,     cudaFuncAttributeMaxDynamicSharedMemorySize, KB_SMEM);

    conv_split<<<NELEM / (256 * 4), 256>>>(Q, K, V);
    swa_scores<<<dim3(32, NTIL, B_DIM), 256, KA_SMEM>>>(M);
    swa_pv<<<dim3(32, 8, B_DIM), 256, KB_SMEM>>>(Out);
}

// round 16
// speedup vs baseline: 1.1586x; 1.0383x over previous
#include <cuda_runtime.h>
#include <cuda_bf16.h>
#include <cstdint>

// SlidingWindowAttention B=4,S=4096,E=1024,W=256 fp32 — mma.sync bf16-split (HMMA).
// conv: Q/K/V fp32 -> bf16 hi/lo scratch (DRAM-bound, at floor).
// KA:   grid (32 qb, 5 tile, 4 b). One CTA = one 128x128 S tile over 16 e-chunks.
//       3-split HMMA, band-skip of fully-masked 16x16 blocks, paired-nbp MMA
//       interleave (4 accumulators in flight), mask+exp2, P -> scratch in
//       A-fragment layout; per-tile l partials -> g_lpart.
// KB:   grid (32 qb, 8 e-chunk, 4 b). 5 key tiles; V via ldmatrix.trans;
//       band-skip; P prefetched one kb ahead; paired-nbp interleave; 1/l scale.
// Both GEMM kernels: single-buffer staging + __launch_bounds__(256,2).

#define S_LEN 4096
#define B_DIM 4
#define E_CH  1024
#define WND   256
#define NTIL  5
#define LOG2E_F 1.4426950408889634f
#define NELEM (B_DIM*S_LEN*E_CH)

__device__ __nv_bfloat16 g_Qh[NELEM], g_Ql[NELEM];
__device__ __nv_bfloat16 g_Kh[NELEM], g_Kl[NELEM];
__device__ __nv_bfloat16 g_Vh[NELEM], g_Vl[NELEM];
__device__ uint32_t g_Ph[B_DIM*32*NTIL*8*8*32*4];   // [b][qb][tile][w][kb][lane][4]
__device__ uint32_t g_Pl[B_DIM*32*NTIL*8*8*32*4];
__device__ float    g_lpart[B_DIM*32*NTIL*128];     // per-tile row sums

__device__ __forceinline__ uint32_t smem_u32(const void* p){
    uint32_t a; asm("{ .reg .u64 t; cvta.to.shared.u64 t, %1; cvt.u32.u64 %0, t; }":"=r"(a):"l"(p)); return a;
}
__device__ __forceinline__ void ldsm4(uint32_t addr, uint32_t r[4]){
    asm volatile("ldmatrix.sync.aligned.m8n8.x4.shared.b16 {%0,%1,%2,%3}, [%4];"
        : "=r"(r[0]),"=r"(r[1]),"=r"(r[2]),"=r"(r[3]) : "r"(addr));
}
__device__ __forceinline__ void ldsm4t(uint32_t addr, uint32_t r[4]){
    asm volatile("ldmatrix.sync.aligned.m8n8.x4.trans.shared.b16 {%0,%1,%2,%3}, [%4];"
        : "=r"(r[0]),"=r"(r[1]),"=r"(r[2]),"=r"(r[3]) : "r"(addr));
}
__device__ __forceinline__ void mma16816(float c[4], const uint32_t a[4], uint32_t b0, uint32_t b1){
    asm volatile("mma.sync.aligned.m16n8k16.row.col.f32.bf16.bf16.f32 "
        "{%0,%1,%2,%3}, {%4,%5,%6,%7}, {%8,%9}, {%0,%1,%2,%3};"
        : "+f"(c[0]),"+f"(c[1]),"+f"(c[2]),"+f"(c[3])
        : "r"(a[0]),"r"(a[1]),"r"(a[2]),"r"(a[3]), "r"(b0),"r"(b1));
}
__device__ __forceinline__ void cpa16(uint32_t dst, const void* src){
    asm volatile("cp.async.cg.shared.global [%0], [%1], 16;" :: "r"(dst), "l"(src) : "memory");
}
#define CP_COMMIT() asm volatile("cp.async.commit_group;" ::: "memory")
#define CP_WAIT(n)  asm volatile("cp.async.wait_group %0;" :: "n"(n) : "memory")

__device__ __forceinline__ void spl(float x, unsigned short& h, unsigned short& l){
    __nv_bfloat16 hb = __float2bfloat16(x);
    h = __bfloat16_as_ushort(hb);
    l = __bfloat16_as_ushort(__float2bfloat16(x - __bfloat162float(hb)));
}
__device__ __forceinline__ uint32_t pack2(float a, float b, uint32_t& lo){
    unsigned short ha, la, hb2, lb2; spl(a, ha, la); spl(b, hb2, lb2);
    lo = (uint32_t)la | ((uint32_t)lb2 << 16);
    return (uint32_t)ha | ((uint32_t)hb2 << 16);
}

// ================= conversion kernel =================
__global__ __launch_bounds__(256) void conv_split(const float* __restrict__ q,
                                                  const float* __restrict__ k,
                                                  const float* __restrict__ v)
{
    int i = (blockIdx.x * 256 + threadIdx.x) * 4;
    if (i >= NELEM) return;
    float4 a = *(const float4*)(q + i);
    float4 b = *(const float4*)(k + i);
    float4 c = *(const float4*)(v + i);
    ushort4 h, l;
    spl(a.x, h.x, l.x); spl(a.y, h.y, l.y); spl(a.z, h.z, l.z); spl(a.w, h.w, l.w);
    *(ushort4*)(g_Qh + i) = h; *(ushort4*)(g_Ql + i) = l;
    spl(b.x, h.x, l.x); spl(b.y, h.y, l.y); spl(b.z, h.z, l.z); spl(b.w, h.w, l.w);
    *(ushort4*)(g_Kh + i) = h; *(ushort4*)(g_Kl + i) = l;
    spl(c.x, h.x, l.x); spl(c.y, h.y, l.y); spl(c.z, h.z, l.z); spl(c.w, h.w, l.w);
    *(ushort4*)(g_Vh + i) = h; *(ushort4*)(g_Vl + i) = l;
}

// ================= kernel A: one S tile + softmax -> P =================
// smem (bf16, 144B/row stride): Qh@0, Ql@18432, Kh@36864, Kl@55296; mask f32 @73728
#define KA_QH 0
#define KA_QL 18432
#define KA_KH 36864
#define KA_KL 55296
#define KA_SMEM (73728 + 512)

__global__ __launch_bounds__(256, 2)
void swa_scores(const int* __restrict__ maskg)
{
    extern __shared__ char sm[];
    const uint32_t smb = smem_u32(sm);
    float* mskS = (float*)(sm + 73728);

    const int t = threadIdx.x, w = t >> 5, lane = t & 31;
    const int qb = blockIdx.x, tile = blockIdx.y, b = blockIdx.z;
    const int q0 = qb * 128;
    const int j0 = q0 - WND + tile * 128;
    const float scale2 = (1.0f / 32.0f) * LOG2E_F;

    const int q_lo = q0 + w * 16 + (lane >> 2);
    const int q_hi = q_lo + 8;
    const int kb_lo = (tile == 0)        ? w : 0;
    const int kb_hi = (tile == NTIL - 1) ? w : 7;

    if (t < 128) {
        int j = j0 + t;
        mskS[t] = (j >= 0 && j < S_LEN && maskg[(long)b * S_LEN + j] != 0) ? 1.0f : 0.0f;
    }

    float c[16][4];
    #pragma unroll
    for (int n = 0; n < 16; n++) { c[n][0]=0.f; c[n][1]=0.f; c[n][2]=0.f; c[n][3]=0.f; }

    for (int ec = 0; ec < 16; ec++) {          // 64-e chunks, single buffer
        #pragma unroll
        for (int i = 0; i < 4; i++) {
            int idx = t + i * 256;             // 0..1023
            int row = idx >> 3, seg = idx & 7;
            long qsrc = ((long)(b * S_LEN + q0 + row)) * E_CH + ec * 64 + seg * 8;
            int jj = j0 + row; jj = jj < 0 ? 0 : (jj >= S_LEN ? S_LEN - 1 : jj);
            long ksrc = ((long)(b * S_LEN + jj)) * E_CH + ec * 64 + seg * 8;
            uint32_t dst = (uint32_t)(row * 144 + seg * 16);
            cpa16(smb + KA_QH + dst, g_Qh + qsrc);
            cpa16(smb + KA_QL + dst, g_Ql + qsrc);
            cpa16(smb + KA_KH + dst, g_Kh + ksrc);
            cpa16(smb + KA_KL + dst, g_Kl + ksrc);
        }
        CP_COMMIT(); CP_WAIT(0);
        __syncthreads();

        const uint32_t arow = (uint32_t)(w * 16 + (lane & 15));
        for (int kbE = 0; kbE < 4; kbE++) {    // e sub-chunks of 16
            uint32_t aoff = arow * 144 + kbE * 32 + (lane >> 4) * 16;
            uint32_t ah[4], al[4];
            ldsm4(smb + KA_QH + aoff, ah);
            ldsm4(smb + KA_QL + aoff, al);
            #pragma unroll
            for (int pb = 0; pb < 4; pb++) {   // nbp pairs: 4 accumulators in flight
                const int n0 = 2 * pb, n1 = n0 + 1;
                const bool a0 = (n0 >= kb_lo) && (n0 <= kb_hi);
                const bool a1 = (n1 >= kb_lo) && (n1 <= kb_hi);
                if (!a0 && !a1) continue;
                uint32_t bh0[4], bl0[4], bh1[4], bl1[4];
                if (a0) {
                    uint32_t brow = (uint32_t)(n0 * 16 + (lane & 7) + ((lane & 16) >> 1));
                    uint32_t boff = brow * 144 + kbE * 32 + ((lane >> 3) & 1) * 16;
                    ldsm4(smb + KA_KH + boff, bh0);
                    ldsm4(smb + KA_KL + boff, bl0);
                }
                if (a1) {
                    uint32_t brow = (uint32_t)(n1 * 16 + (lane & 7) + ((lane & 16) >> 1));
                    uint32_t boff = brow * 144 + kbE * 32 + ((lane >> 3) & 1) * 16;
                    ldsm4(smb + KA_KH + boff, bh1);
                    ldsm4(smb + KA_KL + boff, bl1);
                }
                if (a0 && a1) {                // distance-4 interleave
                    mma16816(c[2*n0  ], ah, bh0[0], bh0[1]);
                    mma16816(c[2*n0+1], ah, bh0[2], bh0[3]);
                    mma16816(c[2*n1  ], ah, bh1[0], bh1[1]);
                    mma16816(c[2*n1+1], ah, bh1[2], bh1[3]);
                    mma16816(c[2*n0  ], ah, bl0[0], bl0[1]);
                    mma16816(c[2*n0+1], ah, bl0[2], bl0[3]);
                    mma16816(c[2*n1  ], ah, bl1[0], bl1[1]);
                    mma16816(c[2*n1+1], ah, bl1[2], bl1[3]);
                    mma16816(c[2*n0  ], al, bh0[0], bh0[1]);
                    mma16816(c[2*n0+1], al, bh0[2], bh0[3]);
                    mma16816(c[2*n1  ], al, bh1[0], bh1[1]);
                    mma16816(c[2*n1+1], al, bh1[2], bh1[3]);
                } else if (a0) {
                    mma16816(c[2*n0  ], ah, bh0[0], bh0[1]);
                    mma16816(c[2*n0+1], ah, bh0[2], bh0[3]);
                    mma16816(c[2*n0  ], ah, bl0[0], bl0[1]);
                    mma16816(c[2*n0+1], ah, bl0[2], bl0[3]);
                    mma16816(c[2*n0  ], al, bh0[0], bh0[1]);
                    mma16816(c[2*n0+1], al, bh0[2], bh0[3]);
                } else {
                    mma16816(c[2*n1  ], ah, bh1[0], bh1[1]);
                    mma16816(c[2*n1+1], ah, bh1[2], bh1[3]);
                    mma16816(c[2*n1  ], ah, bl1[0], bl1[1]);
                    mma16816(c[2*n1+1], ah, bl1[2], bl1[3]);
                    mma16816(c[2*n1  ], al, bh1[0], bh1[1]);
                    mma16816(c[2*n1+1], al, bh1[2], bh1[3]);
                }
            }
        }
        __syncthreads();                       // buffer free for next chunk's stores
    }

    // ---- epilogue: mask + exp2, pack P A-frags, store; l partials ----
    float sum_lo = 0.0f, sum_hi = 0.0f;
    #pragma unroll
    for (int kb = 0; kb < 8; kb++) {
        if (kb < kb_lo || kb > kb_hi) continue;
        float p[8];
        #pragma unroll
        for (int half = 0; half < 2; half++) {
            int nb = 2 * kb + half;
            int col0 = j0 + nb * 8 + 2 * (lane & 3);
            float mk0 = mskS[nb * 8 + 2 * (lane & 3)];
            float mk1 = mskS[nb * 8 + 2 * (lane & 3) + 1];
            bool ok00 = (mk0 > 0.5f) && (abs(q_lo - col0)     <= WND);
            bool ok01 = (mk1 > 0.5f) && (abs(q_lo - col0 - 1) <= WND);
            bool ok10 = (mk0 > 0.5f) && (abs(q_hi - col0)     <= WND);
            bool ok11 = (mk1 > 0.5f) && (abs(q_hi - col0 - 1) <= WND);
            p[half*4+0] = ok00 ? exp2f(c[nb][0] * scale2) : 0.0f;
            p[half*4+1] = ok01 ? exp2f(c[nb][1] * scale2) : 0.0f;
            p[half*4+2] = ok10 ? exp2f(c[nb][2] * scale2) : 0.0f;
            p[half*4+3] = ok11 ? exp2f(c[nb][3] * scale2) : 0.0f;
        }
        sum_lo += p[0] + p[1] + p[4] + p[5];
        sum_hi += p[2] + p[3] + p[6] + p[7];
        uint32_t hr[4], lr[4];
        hr[0] = pack2(p[0], p[1], lr[0]);
        hr[1] = pack2(p[2], p[3], lr[1]);
        hr[2] = pack2(p[4], p[5], lr[2]);
        hr[3] = pack2(p[6], p[7], lr[3]);
        uint32_t idx4 = ((uint32_t)((((b * 32 + qb) * NTIL + tile) * 8 + w) * 8 + kb) * 32 + lane) * 4;
        *(uint4*)(g_Ph + idx4) = make_uint4(hr[0], hr[1], hr[2], hr[3]);
        *(uint4*)(g_Pl + idx4) = make_uint4(lr[0], lr[1], lr[2], lr[3]);
    }
    sum_lo += __shfl_xor_sync(0xffffffffu, sum_lo, 1);
    sum_lo += __shfl_xor_sync(0xffffffffu, sum_lo, 2);
    sum_hi += __shfl_xor_sync(0xffffffffu, sum_hi, 1);
    sum_hi += __shfl_xor_sync(0xffffffffu, sum_hi, 2);
    if ((lane & 3) == 0) {
        int base = ((b * 32 + qb) * NTIL + tile) * 128;
        g_lpart[base + w * 16 + (lane >> 2)]     = sum_lo;
        g_lpart[base + w * 16 + (lane >> 2) + 8] = sum_hi;
    }
}

// ================= kernel B: O chunk = P @ V =================
// smem single buffer: Vh@0, Vl@34816 (128 rows x 136 bf16 = 272B/row)
#define KB_VH 0
#define KB_VL 34816
#define KB_SMEM 69632

__global__ __launch_bounds__(256, 2)
void swa_pv(float* __restrict__ Og)
{
    extern __shared__ char sm[];
    const uint32_t smb = smem_u32(sm);

    const int t = threadIdx.x, w = t >> 5, lane = t & 31;
    const int qb = blockIdx.x, ec2 = blockIdx.y, b = blockIdx.z;
    const int q0 = qb * 128;
    const int e0 = ec2 * 128;

    const int row_lo = w * 16 + (lane >> 2);
    const int q_lo = q0 + row_lo;

    float l_lo = 0.0f, l_hi = 0.0f;
    #pragma unroll
    for (int tl = 0; tl < NTIL; tl++) {
        int base = ((b * 32 + qb) * NTIL + tl) * 128;
        l_lo += g_lpart[base + row_lo];
        l_hi += g_lpart[base + row_lo + 8];
    }
    const float linv_lo = (l_lo > 0.0f) ? (1.0f / l_lo) : 0.0f;
    const float linv_hi = (l_hi > 0.0f) ? (1.0f / l_hi) : 0.0f;

    float c[16][4];
    #pragma unroll
    for (int n = 0; n < 16; n++) { c[n][0]=0.f; c[n][1]=0.f; c[n][2]=0.f; c[n][3]=0.f; }

    for (int tile = 0; tile < NTIL; tile++) {
        const int j0 = q0 - WND + tile * 128;
        const int kb_lo = (tile == 0)        ? w : 0;
        const int kb_hi = (tile == NTIL - 1) ? w : 7;

        // stage V chunk hi/lo (single buffer)
        #pragma unroll
        for (int i = 0; i < 8; i++) {
            int idx = t + i * 256;              // 0..2047
            int k = idx >> 4, seg = idx & 15;   // 128 keys x 16 segs(16B)
            int jj = j0 + k; jj = jj < 0 ? 0 : (jj >= S_LEN ? S_LEN - 1 : jj);
            long src = ((long)(b * S_LEN + jj)) * E_CH + e0 + seg * 8;
            uint32_t dst = (uint32_t)(k * 272 + seg * 16);
            cpa16(smb + KB_VH + dst, g_Vh + src);
            cpa16(smb + KB_VL + dst, g_Vl + src);
        }
        CP_COMMIT(); CP_WAIT(0);
        __syncthreads();

        const uint32_t pstride = ((uint32_t)(b * 32 + qb) * NTIL + tile) * 8 + w;
        // prefetch first active kb's P
        uint4 h4, l4;
        {
            uint32_t idx4 = ((pstride * 8 + (uint32_t)kb_lo) * 32 + lane) * 4;
            h4 = *(const uint4*)(g_Ph + idx4);
            l4 = *(const uint4*)(g_Pl + idx4);
        }
        for (int kb = kb_lo; kb <= kb_hi; kb++) {
            uint4 h4n, l4n;
            if (kb < kb_hi) {                  // prefetch next kb's P under this kb's MMAs
                uint32_t idx4 = ((pstride * 8 + (uint32_t)(kb + 1)) * 32 + lane) * 4;
                h4n = *(const uint4*)(g_Ph + idx4);
                l4n = *(const uint4*)(g_Pl + idx4);
            }
            uint32_t ph[4] = {h4.x, h4.y, h4.z, h4.w};
            uint32_t pl[4] = {l4.x, l4.y, l4.z, l4.w};
            uint32_t vrow = (uint32_t)(kb * 16 + (lane & 7) + ((lane >> 3) & 1) * 8);
            #pragma unroll
            for (int pb = 0; pb < 4; pb++) {   // nbp pairs: 4 accumulators in flight
                const int n0 = 2 * pb, n1 = n0 + 1;
                uint32_t voff0 = vrow * 272 + (n0 * 16 + (lane >> 4) * 8) * 2;
                uint32_t voff1 = vrow * 272 + (n1 * 16 + (lane >> 4) * 8) * 2;
                uint32_t bh0[4], bl0[4], bh1[4], bl1[4];
                ldsm4t(smb + KB_VH + voff0, bh0);
                ldsm4t(smb + KB_VL + voff0, bl0);
                ldsm4t(smb + KB_VH + voff1, bh1);
                ldsm4t(smb + KB_VL + voff1, bl1);
                mma16816(c[2*n0  ], ph, bh0[0], bh0[1]);
                mma16816(c[2*n0+1], ph, bh0[2], bh0[3]);
                mma16816(c[2*n1  ], ph, bh1[0], bh1[1]);
                mma16816(c[2*n1+1], ph, bh1[2], bh1[3]);
                mma16816(c[2*n0  ], ph, bl0[0], bl0[1]);
                mma16816(c[2*n0+1], ph, bl0[2], bl0[3]);
                mma16816(c[2*n1  ], ph, bl1[0], bl1[1]);
                mma16816(c[2*n1+1], ph, bl1[2], bl1[3]);
                mma16816(c[2*n0  ], pl, bh0[0], bh0[1]);
                mma16816(c[2*n0+1], pl, bh0[2], bh0[3]);
                mma16816(c[2*n1  ], pl, bh1[0], bh1[1]);
                mma16816(c[2*n1+1], pl, bh1[2], bh1[3]);
            }
            h4 = h4n; l4 = l4n;
        }
        __syncthreads();                       // buffer free for next tile's stores
    }

    // ---- epilogue: scale rows by 1/l, store this 128-e chunk ----
    float* out_lo = Og + ((long)(b * S_LEN + q_lo)) * E_CH;
    float* out_hi = out_lo + 8L * E_CH;
    #pragma unroll
    for (int nb = 0; nb < 16; nb++) {
        int col = e0 + nb * 8 + 2 * (lane & 3);
        *(float2*)(out_lo + col) = make_float2(c[nb][0] * linv_lo, c[nb][1] * linv_lo);
        *(float2*)(out_hi + col) = make_float2(c[nb][2] * linv_hi, c[nb][3] * linv_hi);
    }
}

// ================= launch =================
extern "C" void kernel_launch(void* const* d_in, const int* in_sizes, int n_in,
                              void* d_out, int out_size)
{
    const float* Q = (const float*)d_in[0];
    const float* K = (const float*)d_in[1];
    const float* V = (const float*)d_in[2];
    const int*   M = (const int*)d_in[3];
    float* Out = (float*)d_out;

    cudaFuncSetAttribute(swa_scores, cudaFuncAttributeMaxDynamicSharedMemorySize, KA_SMEM);
    cudaFuncSetAttribute(swa_pv,     cudaFuncAttributeMaxDynamicSharedMemorySize, KB_SMEM);

    conv_split<<<NELEM / (256 * 4), 256>>>(Q, K, V);
    swa_scores<<<dim3(32, NTIL, B_DIM), 256, KA_SMEM>>>(M);
    swa_pv<<<dim3(32, 8, B_DIM), 256, KB_SMEM>>>(Out);
}